// round 2
// baseline (speedup 1.0000x reference)
#include <cuda_runtime.h>
#include <math.h>

// Fixed shapes from reference setup_inputs: B x 3 x 512 x 960
#define IMG_H 512
#define IMG_W 960
#define NCH 3

#define TW 32          // tile output width  (one warp-lane per column)
#define TH 32          // tile output height (4 rows per warp, 8 warps)
#define SW (TW + 2)    // staged rows/cols incl. 1-px halo
#define PITCH (TW + 2)

#define ALPHA 0.85f
#define C1 (0.01f * 0.01f)
#define C2 (0.03f * 0.03f)
#define EPS2 (0.001f * 0.001f)

// global accumulators: [0]=photo_num, [1]=lr_num, [2]=den (== sum(valid))
__device__ double g_acc[3];

__global__ void init_acc_kernel() {
    if (threadIdx.x < 3) g_acc[threadIdx.x] = 0.0;
}

__global__ __launch_bounds__(256) void stereo_loss_kernel(
    const float* __restrict__ left,
    const float* __restrict__ right,
    const float* __restrict__ d_left,
    const float* __restrict__ d_right,
    const float* __restrict__ nonocc)
{
    const int W = IMG_W, H = IMG_H;
    __shared__ float sA[NCH][SW][PITCH];   // left
    __shared__ float sB[NCH][SW][PITCH];   // warped right
    __shared__ float sD[SW][PITCH];        // d_left

    const int w0 = blockIdx.x * TW;
    const int h0 = blockIdx.y * TH;
    const int b  = blockIdx.z;

    const size_t planeHW = (size_t)H * W;
    const float* Lb  = left    + (size_t)b * NCH * planeHW;
    const float* Rb  = right   + (size_t)b * NCH * planeHW;
    const float* Db  = d_left  + (size_t)b * planeHW;
    const float* DRb = d_right + (size_t)b * planeHW;
    const float* Nb  = nonocc  + (size_t)b * planeHW;

    // ---- halo fill (zero outside image; zero-fill + true count == count_include_pad=False) ----
    for (int idx = threadIdx.x; idx < SW * SW; idx += 256) {
        int i = idx / SW;
        int j = idx - i * SW;
        int gh = h0 - 1 + i;
        int gw = w0 - 1 + j;
        if (gh >= 0 && gh < H && gw >= 0 && gw < W) {
            float d = Db[(size_t)gh * W + gw];
            sD[i][j] = d;
            float x  = (float)gw - d;
            float x0 = floorf(x);
            float wx = x - x0;
            int   xi = (int)x0;
            int x0i = min(max(xi, 0), W - 1);
            int x1i = min(max(xi + 1, 0), W - 1);
            const float* rrow = Rb + (size_t)gh * W;
            const float* lrow = Lb + (size_t)gh * W;
            #pragma unroll
            for (int c = 0; c < NCH; c++) {
                float v0 = rrow[(size_t)c * planeHW + x0i];
                float v1 = rrow[(size_t)c * planeHW + x1i];
                sB[c][i][j] = (1.0f - wx) * v0 + wx * v1;
                sA[c][i][j] = lrow[(size_t)c * planeHW + gw];
            }
        } else {
            sD[i][j] = 0.0f;
            #pragma unroll
            for (int c = 0; c < NCH; c++) { sA[c][i][j] = 0.0f; sB[c][i][j] = 0.0f; }
        }
    }
    __syncthreads();

    const int tx  = threadIdx.x & 31;        // lane = x column
    const int wid = threadIdx.x >> 5;        // warp = 4-row strip
    const int r0  = wid * 4;
    const int gw  = w0 + tx;

    // ---- per-row precompute: validity weight, 1/n, source x ----
    float wv[4], invn[4], xs[4], dl4[4];
    float accD = 0.0f;
    const float colsF = 1.0f + (gw > 0 ? 1.0f : 0.0f) + (gw < W - 1 ? 1.0f : 0.0f);
    #pragma unroll
    for (int k = 0; k < 4; k++) {
        const int r  = r0 + k;
        const int gh = h0 + r;
        float dl = sD[r + 1][tx + 1];
        float x  = (float)gw - dl;
        float gx = 2.0f * x / (float)(W - 1) - 1.0f;
        float vb = (gx >= -1.0f && gx <= 1.0f) ? 1.0f : 0.0f;
        wv[k] = vb * Nb[(size_t)gh * W + gw];
        accD += wv[k];
        float rowsF = 1.0f + (gh > 0 ? 1.0f : 0.0f) + (gh < H - 1 ? 1.0f : 0.0f);
        invn[k] = 1.0f / (rowsF * colsF);
        xs[k]  = x;
        dl4[k] = dl;
    }

    // ---- separable 3x3 moment pooling with rotating register window ----
    // HSUM over smem row s: 5 horizontal 3-sums + center pixel values.
    #define HSUM(c, s, Hv, cA, cB) {                                        \
        float a0 = sA[c][s][tx], a1 = sA[c][s][tx + 1], a2 = sA[c][s][tx + 2]; \
        float b0 = sB[c][s][tx], b1 = sB[c][s][tx + 1], b2 = sB[c][s][tx + 2]; \
        Hv[0] = a0 + a1 + a2;                                               \
        Hv[1] = b0 + b1 + b2;                                               \
        Hv[2] = fmaf(a0, a0, fmaf(a1, a1, a2 * a2));                        \
        Hv[3] = fmaf(b0, b0, fmaf(b1, b1, b2 * b2));                        \
        Hv[4] = fmaf(a0, b0, fmaf(a1, b1, a2 * b2));                        \
        cA = a1; cB = b1; }

    float accS[4]  = {0.f, 0.f, 0.f, 0.f};
    float accL1[4] = {0.f, 0.f, 0.f, 0.f};

    #pragma unroll
    for (int c = 0; c < NCH; c++) {
        float hA[5], hBv[5], hC[5];
        float cA1, cB1, cA2, cB2, du0, du1;
        HSUM(c, r0 + 0, hA, du0, du1);       // hsum row r0-1
        HSUM(c, r0 + 1, hBv, cA1, cB1);      // hsum row r0   (center = pixel r0)
        #pragma unroll
        for (int k = 0; k < 4; k++) {
            HSUM(c, r0 + 2 + k, hC, cA2, cB2);   // hsum row r0+1+k
            float inv = invn[k];
            float sx  = hA[0] + hBv[0] + hC[0];
            float sy  = hA[1] + hBv[1] + hC[1];
            float sxx = hA[2] + hBv[2] + hC[2];
            float syy = hA[3] + hBv[3] + hC[3];
            float sxy = hA[4] + hBv[4] + hC[4];
            float mux   = sx * inv;
            float muy   = sy * inv;
            float sigx  = sxx * inv - mux * mux;
            float sigy  = syy * inv - muy * muy;
            float sigxy = sxy * inv - mux * muy;
            float num = (2.0f * mux * muy + C1) * (2.0f * sigxy + C2);
            float den = (mux * mux + muy * muy + C1) * (sigx + sigy + C2);
            float ssim = num / (den + 1e-12f);
            accS[k] += fminf(fmaxf((1.0f - ssim) * 0.5f, 0.0f), 1.0f);
            float d0 = cA1 - cB1;
            accL1[k] += sqrtf(fmaf(d0, d0, EPS2));
            // rotate window
            #pragma unroll
            for (int q = 0; q < 5; q++) { hA[q] = hBv[q]; hBv[q] = hC[q]; }
            cA1 = cA2; cB1 = cB2;
        }
    }
    #undef HSUM

    // ---- finalize rows: photometric + LR consistency ----
    float accP = 0.0f, accL = 0.0f;
    #pragma unroll
    for (int k = 0; k < 4; k++) {
        float photo = ALPHA * (accS[k] * (1.0f / 3.0f)) +
                      (1.0f - ALPHA) * (accL1[k] * (1.0f / 3.0f));
        accP += photo * wv[k];
        if (wv[k] != 0.0f) {
            const int gh = h0 + r0 + k;
            float x   = xs[k];
            float x0f = floorf(x);
            float wx  = x - x0f;
            int   xi  = (int)x0f;
            int x0i = min(max(xi, 0), W - 1);
            int x1i = min(max(xi + 1, 0), W - 1);
            const float* drow = DRb + (size_t)gh * W;
            float drw = (1.0f - wx) * drow[x0i] + wx * drow[x1i];
            float dd = dl4[k] - drw;
            accL += sqrtf(fmaf(dd, dd, EPS2)) * wv[k];
        }
    }

    // ---- block reduction ----
    #pragma unroll
    for (int o = 16; o > 0; o >>= 1) {
        accP += __shfl_down_sync(0xFFFFFFFFu, accP, o);
        accL += __shfl_down_sync(0xFFFFFFFFu, accL, o);
        accD += __shfl_down_sync(0xFFFFFFFFu, accD, o);
    }
    __shared__ float red[3][8];
    int lane = threadIdx.x & 31;
    if (lane == 0) {
        red[0][wid] = accP;
        red[1][wid] = accL;
        red[2][wid] = accD;
    }
    __syncthreads();
    if (threadIdx.x == 0) {
        double p = 0.0, l = 0.0, d = 0.0;
        #pragma unroll
        for (int i = 0; i < 8; i++) {
            p += (double)red[0][i];
            l += (double)red[1][i];
            d += (double)red[2][i];
        }
        atomicAdd(&g_acc[0], p);
        atomicAdd(&g_acc[1], l);
        atomicAdd(&g_acc[2], d);
    }
}

__global__ void finalize_kernel(float* __restrict__ out, int total_px) {
    if (threadIdx.x == 0) {
        double den   = g_acc[2];
        double photo = g_acc[0] / (den + 1e-6);
        double lr    = g_acc[1] / (den + 1e-6);
        out[0] = (float)(photo + 0.2 * lr);        // total (W_PHOTO=1, W_LR=0.2)
        out[1] = (float)photo;                     // photo_loss
        out[2] = (float)lr;                        // lr_loss
        out[3] = (float)(den / (double)total_px);  // valid_ratio
    }
}

extern "C" void kernel_launch(void* const* d_in, const int* in_sizes, int n_in,
                              void* d_out, int out_size) {
    const float* left    = (const float*)d_in[0];
    const float* right   = (const float*)d_in[1];
    const float* d_left  = (const float*)d_in[2];
    const float* d_right = (const float*)d_in[3];
    const float* nonocc  = (const float*)d_in[4];
    float* out = (float*)d_out;

    int B = in_sizes[2] / (IMG_H * IMG_W);   // d_left is [B,1,H,W]

    init_acc_kernel<<<1, 32>>>();

    dim3 grid(IMG_W / TW, IMG_H / TH, B);
    stereo_loss_kernel<<<grid, 256>>>(left, right, d_left, d_right, nonocc);

    finalize_kernel<<<1, 32>>>(out, B * IMG_H * IMG_W);
}